// round 13
// baseline (speedup 1.0000x reference)
#include <cuda_runtime.h>
#include <math.h>

#define NFRAMES   16384
#define HOPC      240
#define HOP2XC    480
#define L2X       (NFRAMES*HOP2XC)      /* 7,864,320 */
#define NSTFT     (NFRAMES+1)           /* 16385 */
#define OUTLEN    (NFRAMES*HOPC)        /* 3,932,160 */
#define PI_D      3.14159265358979323846

#define LEN48   (48*1024+1)
#define LEN144  (144*1024+1)
#define LEN432  (432*1024+1)

#define NCHUNK  128
#define CHUNKSZ 128

// ---------------- static device scratch ----------------
__device__ float  g_p2x[L2X];
__device__ float  g_ybuf[NSTFT * 512];
__device__ double g_ex[NFRAMES];
__device__ double g_csum[NCHUNK];
__device__ double g_c1[NFRAMES];
__device__ double g_c2h[NFRAMES];
__device__ float  g_af[NFRAMES];
__device__ float  g_bf[NFRAMES];
__device__ unsigned char g_vuv[NFRAMES + 1];
__device__ float  g_w1024[1024];
__device__ float  g_w512[512];
__device__ float  g_ienv[240];
__device__ float2 g_tw[1024];                 // exp(-2*pi*i*k/1024)
__device__ float  g_trans[HOP2XC];
__device__ float2 g_pr48[LEN48];
__device__ float2 g_pr144[LEN144];
__device__ float2 g_pr432[LEN432];

// ---------------- helpers ----------------
__device__ __forceinline__ float2 cmul(float2 a, float2 b) {
    return make_float2(a.x * b.x - a.y * b.y, a.x * b.y + a.y * b.x);
}
__device__ __forceinline__ float2 cadd(float2 a, float2 b) { return make_float2(a.x + b.x, a.y + b.y); }
__device__ __forceinline__ float2 csub(float2 a, float2 b) { return make_float2(a.x - b.x, a.y - b.y); }
__device__ __forceinline__ float2 jmul(float2 a) { return make_float2(-a.y, a.x); }   // i*a

#define PADI(i) ((i) + ((i) >> 3))
#define PADSZ   (512 + 64)

__device__ __forceinline__ float hannf512(int n) {
    return (float)(0.5 - 0.5 * cos(2.0 * PI_D * (double)n / 512.0));
}

// ---------------- K1: fused per-frame setup + chunk scan (replaces init-frames+scan1) -
__global__ void __launch_bounds__(CHUNKSZ) k_scan1(const float* __restrict__ f0) {
    __shared__ double warpsum[4];
    const int t = threadIdx.x;
    const int lane = t & 31;
    const int wid = t >> 5;
    const int i = blockIdx.x * CHUNKSZ + t;

    const double fi = (double)f0[i];
    const double fn = (i + 1 < NFRAMES) ? (double)f0[i + 1] : 0.0;
    const double a = (fi != 0.0) ? fi : fn;
    const double b = (fn != 0.0) ? fn : fi;
    g_af[i] = (float)a;
    g_bf[i] = (float)b;
    g_c1[i] = a / 96000.0;
    g_c2h[i] = (b - a) / (2.0 * 480.0 * 96000.0);
    unsigned char m = 0;
    if (fi >= 500.0 && fi < 1500.0) m |= 1;
    if (fi >= (24000.0 / 144.0) && fi < 500.0) m |= 2;
    if (fi >= (24000.0 / 432.0) && fi < (24000.0 / 144.0)) m |= 4;
    g_vuv[i] = m;
    if (i == NFRAMES - 1) g_vuv[NFRAMES] = 0;

    const double s = (480.0 * a + (b - a) * (114960.0 / 480.0)) / 96000.0;

    // 128-thread inclusive scan
    double v = s;
    #pragma unroll
    for (int off = 1; off < 32; off <<= 1) {
        double n = __shfl_up_sync(0xffffffffu, v, off);
        if (lane >= off) v += n;
    }
    if (lane == 31) warpsum[wid] = v;
    __syncthreads();
    if (t == 0) {
        double acc = 0.0;
        #pragma unroll
        for (int w = 0; w < 4; w++) { double x = warpsum[w]; warpsum[w] = acc; acc += x; }
    }
    __syncthreads();
    const double incl = v + warpsum[wid];
    g_ex[i] = incl - s;
    if (t == CHUNKSZ - 1) g_csum[blockIdx.x] = incl;
}

// ---------------- K0: tables only (pairs vectorized 2/thread + spread trig) ----------
__device__ __forceinline__ void build_pairs(const float* __restrict__ py, float2* __restrict__ pr,
                                            int LEN, int j) {
    const int HALF = (LEN - 1) / 2;
    if (j < HALF) {
        const float2 ab = *(const float2*)(py + 2 * j);   // py[2j], py[2j+1]
        const float c = py[2 * j + 2];
        float4 o;
        o.x = ab.x; o.y = ab.y;                            // pr[2j]   = {py[2j], py[2j+1]}
        o.z = ab.y; o.w = c;                               // pr[2j+1] = {py[2j+1], py[2j+2]}
        *(float4*)(pr + 2 * j) = o;
    } else if (j == HALF) {
        const float last = py[LEN - 1];
        pr[LEN - 1] = make_float2(last, last);             // clamped final pair
    }
}

__global__ void k_init(const float* __restrict__ py48, const float* __restrict__ py144,
                       const float* __restrict__ py432) {
    int j = blockIdx.x * blockDim.x + threadIdx.x;
    build_pairs(py48, g_pr48, LEN48, j);
    build_pairs(py144, g_pr144, LEN144, j);
    build_pairs(py432, g_pr432, LEN432, j);
    // spread 1024 fp64-trig items across the grid: one per 216 threads
    if ((j % 216) == 0) {
        int k = j / 216;
        if (k < 1024) {
            g_w1024[k] = (float)(0.5 - 0.5 * cos(2.0 * PI_D * (double)k / 1024.0));
            double ang = -2.0 * PI_D * (double)k / 1024.0;
            g_tw[k] = make_float2((float)cos(ang), (float)sin(ang));
            if (k < 512) g_w512[k] = hannf512(k);
            if (k < HOP2XC) {
                double s = sin(((double)k / (double)HOP2XC) * (PI_D * 0.5));
                g_trans[k] = (float)(s * s);
            }
            if (k < 240) {
                float w0 = hannf512(k), w1 = hannf512(k + 240);
                float env = ((k <= 31) ? hannf512(k + 480) * hannf512(k + 480) : 0.0f)
                            + w1 * w1 + w0 * w0;
                g_ienv[k] = 1.0f / env;
            }
        }
    }
}

// ---------------- K3: excitation (inline chunk-base scan; fp64 phase) ----------------
__device__ __forceinline__ float band_lookup(const float2* __restrict__ pair, int maxi,
                                             float phase, float tr, float v0, float v1) {
    if (v0 == 0.0f && v1 == 0.0f) return 0.0f;
    float mask = v0 + (v1 - v0) * tr;
    float idxf = phase * (float)maxi;
    idxf = fminf(fmaxf(idxf, 0.0f), (float)maxi);
    int lo = (int)floorf(idxf);
    float tt = idxf - (float)lo;
    float2 p = __ldg(pair + lo);
    return mask * (p.x + (p.y - p.x) * tt);
}

__global__ void __launch_bounds__(256) k_gen() {
    __shared__ double sh_cbase[NCHUNK];
    // warp 0: scan the 128 chunk sums (4 per lane)
    if (threadIdx.x < 32) {
        const int lane = threadIdx.x;
        double c[4];
        double s = 0.0;
        #pragma unroll
        for (int r = 0; r < 4; r++) { c[r] = g_csum[lane * 4 + r]; s += c[r]; }
        double v = s;
        #pragma unroll
        for (int off = 1; off < 32; off <<= 1) {
            double n = __shfl_up_sync(0xffffffffu, v, off);
            if (lane >= off) v += n;
        }
        double acc = v - s;       // exclusive prefix of this lane's group
        #pragma unroll
        for (int r = 0; r < 4; r++) { sh_cbase[lane * 4 + r] = acc; acc += c[r]; }
    }
    __syncthreads();

    const int t = blockIdx.x * blockDim.x + threadIdx.x;
    const int s0 = t * 4;
    const int i = s0 / 480;
    const int j0 = s0 - i * 480;

    const double base0 = sh_cbase[i >> 7] + g_ex[i];
    const double base = base0 - floor(base0);
    const double c1 = g_c1[i], c2h = g_c2h[i];
    const float af = g_af[i], bf = g_bf[i];
    const unsigned vi = g_vuv[i], vn = g_vuv[i + 1];
    const float v48a = (float)(vi & 1),         v48b = (float)(vn & 1);
    const float v144a = (float)((vi >> 1) & 1), v144b = (float)((vn >> 1) & 1);
    const float v432a = (float)((vi >> 2) & 1), v432b = (float)((vn >> 2) & 1);

    float ph[4], trv[4], f0cv[4];
    #pragma unroll
    for (int r = 0; r < 4; r++) {
        const double jd = (double)(j0 + r);
        const double u = base + (jd + 1.0) * c1 + (jd * (jd + 1.0)) * c2h;
        ph[r] = (float)(u - floor(u));
        trv[r] = g_trans[j0 + r];
        f0cv[r] = af + (bf - af) * ((float)(j0 + r) * (1.0f / 480.0f));
    }

    float4 out;
    float* op = (float*)&out;
    #pragma unroll
    for (int r = 0; r < 4; r++) {
        float acc = 0.0f;
        acc += band_lookup(g_pr48, 48 * 1024, ph[r], trv[r], v48a, v48b);
        acc += band_lookup(g_pr144, 144 * 1024, ph[r], trv[r], v144a, v144b);
        acc += band_lookup(g_pr432, 432 * 1024, ph[r], trv[r], v432a, v432b);
        op[r] = acc * f0cv[r] * (1.0f / 48000.0f);
    }
    *(float4*)(g_p2x + s0) = out;
}

// ---------------- K4: fused-load FFT512 (8·8·8) + packed IFFT256 (4·8·8, fused store) -
__device__ __forceinline__ void dft8(const float2 x[8], float2 Y[8]) {
    float2 ea = cadd(x[0], x[4]), eb = csub(x[0], x[4]);
    float2 ec = cadd(x[2], x[6]), ed = csub(x[2], x[6]);
    float2 E0 = cadd(ea, ec), E2 = csub(ea, ec);
    float2 E1 = csub(eb, jmul(ed)), E3 = cadd(eb, jmul(ed));

    float2 oa = cadd(x[1], x[5]), ob = csub(x[1], x[5]);
    float2 oc = cadd(x[3], x[7]), od = csub(x[3], x[7]);
    float2 O0 = cadd(oa, oc), O2 = csub(oa, oc);
    float2 O1 = csub(ob, jmul(od)), O3 = cadd(ob, jmul(od));

    const float C = 0.70710678118654752440f;
    float2 T1 = make_float2(C * (O1.x + O1.y), C * (O1.y - O1.x));
    float2 T2 = make_float2(O2.y, -O2.x);
    float2 T3 = make_float2(C * (O3.y - O3.x), -C * (O3.x + O3.y));

    Y[0] = cadd(E0, O0); Y[4] = csub(E0, O0);
    Y[1] = cadd(E1, T1); Y[5] = csub(E1, T1);
    Y[2] = cadd(E2, T2); Y[6] = csub(E2, T2);
    Y[3] = cadd(E3, T3); Y[7] = csub(E3, T3);
}

__device__ __forceinline__ void twiddle_store8(float2* __restrict__ dst, const float2 Y[8],
                                               int p, int q, int S, int M) {
    if (p == 0) {
        #pragma unroll
        for (int r = 0; r < 8; r++) dst[PADI(q + S * r)] = Y[r];
    } else {
        const float2 w1 = __ldg(&g_tw[p * M]);
        const float2 w2 = cmul(w1, w1);
        const float2 w3 = cmul(w2, w1);
        const float2 w4 = cmul(w2, w2);
        const float2 w5 = cmul(w4, w1);
        const float2 w6 = cmul(w4, w2);
        const float2 w7 = cmul(w4, w3);
        dst[PADI(q + S * (8 * p + 0))] = Y[0];
        dst[PADI(q + S * (8 * p + 1))] = cmul(w1, Y[1]);
        dst[PADI(q + S * (8 * p + 2))] = cmul(w2, Y[2]);
        dst[PADI(q + S * (8 * p + 3))] = cmul(w3, Y[3]);
        dst[PADI(q + S * (8 * p + 4))] = cmul(w4, Y[4]);
        dst[PADI(q + S * (8 * p + 5))] = cmul(w5, Y[5]);
        dst[PADI(q + S * (8 * p + 6))] = cmul(w6, Y[6]);
        dst[PADI(q + S * (8 * p + 7))] = cmul(w7, Y[7]);
    }
}

template<int N, int S>
__device__ __forceinline__ void step8(const float2* __restrict__ src, float2* __restrict__ dst,
                                      int t) {
    constexpr int N1 = N / 8;
    constexpr int M = 1024 / N;
    const int p = t / S;
    const int q = t - p * S;
    float2 x[8], Y[8];
    #pragma unroll
    for (int r = 0; r < 8; r++) x[r] = src[PADI(q + S * (p + r * N1))];
    dft8(x, Y);
    twiddle_store8(dst, Y, p, q, S, M);
}

template<int N, int S>
__device__ __forceinline__ void step4(const float2* __restrict__ src, float2* __restrict__ dst,
                                      int t) {
    constexpr int N1 = N / 4;
    constexpr int M = 1024 / N;
    const int p = t / S;
    const int q = t - p * S;
    float2 a = src[PADI(q + S * p)];
    float2 b = src[PADI(q + S * (p + N1))];
    float2 c = src[PADI(q + S * (p + 2 * N1))];
    float2 d = src[PADI(q + S * (p + 3 * N1))];
    float2 apc = cadd(a, c), amc = csub(a, c);
    float2 bpd = cadd(b, d), jbmd = jmul(csub(b, d));
    float2 Y0 = cadd(apc, bpd);
    float2 Y1 = csub(amc, jbmd);
    float2 Y2 = csub(apc, bpd);
    float2 Y3 = cadd(amc, jbmd);
    const float2 w1 = __ldg(&g_tw[p * M]);
    const float2 w2 = cmul(w1, w1);
    const float2 w3 = cmul(w2, w1);
    dst[PADI(q + S * (4 * p + 0))] = Y0;
    dst[PADI(q + S * (4 * p + 1))] = cmul(w1, Y1);
    dst[PADI(q + S * (4 * p + 2))] = cmul(w2, Y2);
    dst[PADI(q + S * (4 * p + 3))] = cmul(w3, Y3);
}

#define FPB 4

__global__ void __launch_bounds__(64 * FPB) k_fft() {
    __shared__ float2 Ub[FPB][PADSZ];
    __shared__ float2 Vb[FPB][PADSZ];
    const int tid = threadIdx.x;
    const int sub = tid >> 6;
    const int t = tid & 63;
    const int frame = blockIdx.x * FPB + sub;
    const bool valid = (frame < NSTFT);

    float2* U = Ub[sub];
    float2* V = Vb[sub];

    // ---- fused: gmem load + window + pack + first radix-8 stage (S=1, p=t, q=0) ----
    {
        float2 x[8], Y[8];
        #pragma unroll
        for (int r = 0; r < 8; r++) {
            const int n0 = t + 64 * r;
            float xe = 0.0f, xo = 0.0f;
            if (valid) {
                int ge = frame * HOP2XC - 512 + 2 * n0;
                if (ge >= 0 && ge + 1 < L2X) {
                    float2 v = *(const float2*)(g_p2x + ge);
                    xe = v.x; xo = v.y;
                } else {
                    int go = ge + 1;
                    if (ge < 0) ge = -ge;
                    if (ge >= L2X) ge = 2 * L2X - 2 - ge;
                    if (go < 0) go = -go;
                    if (go >= L2X) go = 2 * L2X - 2 - go;
                    xe = g_p2x[ge];
                    xo = g_p2x[go];
                }
                xe *= g_w1024[2 * n0];
                xo *= g_w1024[2 * n0 + 1];
            }
            x[r] = make_float2(xe, xo);
        }
        dft8(x, Y);
        twiddle_store8(V, Y, t, 0, 1, 2);     // N=512: S=1, M=2
    }
    __syncthreads();

    step8<64, 8>(V, U, t);   __syncthreads();
    step8<8, 64>(U, V, t);   __syncthreads();

    // unpack real-FFT bins X[0..256], build conj of irfft-256 packing in U[0..255]
    for (int j = t; j <= 128; j += 64) {
        const float2 Zj = V[PADI(j)];
        const float2 Zmj = V[PADI((512 - j) & 511)];
        float2 E = make_float2(0.5f * (Zj.x + Zmj.x), 0.5f * (Zj.y - Zmj.y));
        float2 O = make_float2(0.5f * (Zj.y + Zmj.y), -0.5f * (Zj.x - Zmj.x));
        float2 Xa = cadd(E, cmul(__ldg(&g_tw[j]), O));
        if (j == 0) {
            const float X0r = Xa.x;
            const float X256r = V[PADI(256)].x;
            U[PADI(0)] = make_float2(0.5f * (X0r + X256r), -0.5f * (X0r - X256r));
        } else {
            const int jp = 256 - j;
            const float2 Zk = V[PADI(jp)];
            const float2 Zmk = V[PADI(256 + j)];
            float2 E2 = make_float2(0.5f * (Zk.x + Zmk.x), 0.5f * (Zk.y - Zmk.y));
            float2 O2 = make_float2(0.5f * (Zk.y + Zmk.y), -0.5f * (Zk.x - Zmk.x));
            float2 Xb = cadd(E2, cmul(__ldg(&g_tw[jp]), O2));

            const float2 t2 = __ldg(&g_tw[2 * j]);
            const float2 tp = make_float2(t2.x, -t2.y);
            const float2 tpn = make_float2(-t2.x, -t2.y);

            float2 S1 = make_float2(Xa.x + Xb.x, Xa.y - Xb.y);
            float2 D1 = make_float2(Xa.x - Xb.x, Xa.y + Xb.y);
            float2 zt = jmul(cmul(tp, D1));
            float2 zj = make_float2(0.5f * (S1.x + zt.x), 0.5f * (S1.y + zt.y));
            U[PADI(j)] = make_float2(zj.x, -zj.y);

            float2 S2 = make_float2(Xb.x + Xa.x, Xb.y - Xa.y);
            float2 D2 = make_float2(Xb.x - Xa.x, Xb.y + Xa.y);
            float2 zt2 = jmul(cmul(tpn, D2));
            float2 zp = make_float2(0.5f * (S2.x + zt2.x), 0.5f * (S2.y + zt2.y));
            U[PADI(jp)] = make_float2(zp.x, -zp.y);
        }
    }
    __syncthreads();

    // 256-pt forward FFT of conj(z) as 4·8·8: two smem stages + fused-store final
    step4<256, 1>(U, V, t);  __syncthreads();
    if (t < 32) step8<64, 4>(V, U, t);
    __syncthreads();

    // final radix-8 (N=8, S=32, p=0): 32 threads, outputs m = t + 32r, straight to gmem
    if (valid && t < 32) {
        float2 x[8], Y[8];
        #pragma unroll
        for (int r = 0; r < 8; r++) x[r] = U[PADI(t + 32 * r)];
        dft8(x, Y);
        #pragma unroll
        for (int r = 0; r < 8; r++) {
            const int m = t + 32 * r;
            float2 o;
            o.x = Y[r].x * (1.0f / 256.0f) * g_w512[2 * m];
            o.y = -Y[r].y * (1.0f / 256.0f) * g_w512[2 * m + 1];
            *(float2*)(g_ybuf + frame * 512 + 2 * m) = o;
        }
    }
}

// ---------------- K5: OLA, 4 samples/thread, float4 ----------------
__device__ __forceinline__ float ola_generic(int s) {
    int tlo = (s >= 512) ? (s - 511 + 239) / 240 : 0;
    int thi = s / 240;
    if (thi > NFRAMES) thi = NFRAMES;
    float sig = 0.0f, env = 0.0f;
    for (int t = tlo; t <= thi; t++) {
        const int m = s - 240 * t;
        const float w = g_w512[m];
        sig += g_ybuf[t * 512 + m];
        env += w * w;
    }
    return (env > 1e-11f) ? (sig / env) : 0.0f;
}

__global__ void __launch_bounds__(256) k_ola(float* __restrict__ out) {
    const int idx = blockIdx.x * blockDim.x + threadIdx.x;   // OUTLEN/4 threads
    const int n0 = idx * 4;
    if (n0 >= OUTLEN) return;
    const int s = n0 + 256;                                   // s % 4 == 0

    if (s >= 512 && s <= 16384 * 240 + 236) {
        const int thi = s / 240;
        const int r0 = s - 240 * thi;                         // 0..236, mult of 4
        const float4 v0 = *(const float4*)(g_ybuf + thi * 512 + r0);
        const float4 v1 = *(const float4*)(g_ybuf + (thi - 1) * 512 + r0 + 240);
        float4 sig = make_float4(v0.x + v1.x, v0.y + v1.y, v0.z + v1.z, v0.w + v1.w);
        if (r0 <= 28) {
            const float4 v2 = *(const float4*)(g_ybuf + (thi - 2) * 512 + r0 + 480);
            sig.x += v2.x; sig.y += v2.y; sig.z += v2.z; sig.w += v2.w;
        }
        const float4 ie = *(const float4*)(g_ienv + r0);
        float4 o;
        o.x = sig.x * ie.x;
        o.y = sig.y * ie.y;
        o.z = sig.z * ie.z;
        o.w = sig.w * ie.w;
        *(float4*)(out + n0) = o;
    } else {
        #pragma unroll
        for (int k = 0; k < 4; k++)
            if (n0 + k < OUTLEN) out[n0 + k] = ola_generic(s + k);
    }
}

// ---------------- launcher (5 kernels) ----------------
extern "C" void kernel_launch(void* const* d_in, const int* in_sizes, int n_in,
                              void* d_out, int out_size) {
    const float* f0    = (const float*)d_in[0];
    const float* py48  = (const float*)d_in[1];
    const float* py144 = (const float*)d_in[2];
    const float* py432 = (const float*)d_in[3];
    float* out = (float*)d_out;
    (void)in_sizes; (void)n_in; (void)out_size;

    k_scan1<<<NCHUNK, CHUNKSZ>>>(f0);
    k_init<<<(LEN432 / 2 + 256) / 256, 256>>>(py48, py144, py432);
    k_gen<<<L2X / 4 / 256, 256>>>();
    k_fft<<<(NSTFT + FPB - 1) / FPB, 64 * FPB>>>();
    k_ola<<<(OUTLEN / 4 + 255) / 256, 256>>>(out);
}